// round 16
// baseline (speedup 1.0000x reference)
#include <cuda_runtime.h>
#include <cstdint>

// MultiIndexSelect: out[to_k[i]] = mat_k[from_k[i]], k=0..2, L=400000, D=64 f32.
// Row = 256 B = 16 float4 slots. cp.async gathers into per-thread smem slots
// (register-free in-flight). R15 (128thr/U8): 92.4us, DRAM 70.1%, achieved occ
// 69% < theoretical 87% -> carveout-limited. R16: UNROLL=10 (20KB smem, 15000
// blocks exact) + request max shared carveout. occ*MLP product 5.5 -> ~6.9.

static constexpr int UNROLL  = 10;
static constexpr int THREADS = 128;

__global__ __launch_bounds__(THREADS) void multi_index_select_kernel(
    const float4* __restrict__ m0,
    const float4* __restrict__ m1,
    const float4* __restrict__ m2,
    const int* __restrict__ f0,
    const int* __restrict__ f1,
    const int* __restrict__ f2,
    const int* __restrict__ t0,
    const int* __restrict__ t1,
    const int* __restrict__ t2,
    float4* __restrict__ out,
    int L)
{
    __shared__ float4 buf[THREADS * UNROLL];            // 20 KB, private slot per (thread,u)

    const unsigned total = 3u * (unsigned)L * 16u;      // 19.2M slots
    const unsigned base  = blockIdx.x * (THREADS * UNROLL) + threadIdx.x;

    const unsigned smem_base =
        (unsigned)__cvta_generic_to_shared(buf) + threadIdx.x * 16u;

    unsigned dslot[UNROLL];

    if (base + (UNROLL - 1) * THREADS < total) {
        // Fast path (every block for L=400000): branchless, all index loads +
        // UNROLL register-free gathers back-to-back, one commit group.
        #pragma unroll
        for (int u = 0; u < UNROLL; u++) {
            unsigned tid  = base + u * THREADS;
            unsigned row  = tid >> 4;
            unsigned lane = tid & 15u;
            const float4* __restrict__ mat;
            int src, dst;
            if (row < (unsigned)L) {
                mat = m0; src = __ldg(&f0[row]);        dst = __ldg(&t0[row]);
            } else if (row < 2u * (unsigned)L) {
                unsigned r = row - (unsigned)L;
                mat = m1; src = __ldg(&f1[r]);          dst = __ldg(&t1[r]);
            } else {
                unsigned r = row - 2u * (unsigned)L;
                mat = m2; src = __ldg(&f2[r]);          dst = __ldg(&t2[r]);
            }
            dslot[u] = (unsigned)dst * 16u + lane;
            const float4* gsrc = &mat[(size_t)src * 16u + lane];
            unsigned saddr = smem_base + (unsigned)(u * THREADS) * 16u;
            asm volatile("cp.async.cg.shared.global [%0], [%1], 16;\n"
                         :: "r"(saddr), "l"(gsrc) : "memory");
        }
        asm volatile("cp.async.commit_group;\n" ::: "memory");
        asm volatile("cp.async.wait_group 0;\n"  ::: "memory");

        #pragma unroll
        for (int u = 0; u < UNROLL; u++) {
            float4 v = buf[u * THREADS + threadIdx.x];
            __stcs(&out[dslot[u]], v);
        }
    } else {
        // Generic tail (unused for L=400000).
        #pragma unroll
        for (int u = 0; u < UNROLL; u++) {
            unsigned tid = base + u * THREADS;
            if (tid >= total) continue;
            unsigned row  = tid >> 4;
            unsigned lane = tid & 15u;
            const float4* __restrict__ mat;
            int src, dst;
            if (row < (unsigned)L) {
                mat = m0; src = __ldg(&f0[row]);        dst = __ldg(&t0[row]);
            } else if (row < 2u * (unsigned)L) {
                unsigned r = row - (unsigned)L;
                mat = m1; src = __ldg(&f1[r]);          dst = __ldg(&t1[r]);
            } else {
                unsigned r = row - 2u * (unsigned)L;
                mat = m2; src = __ldg(&f2[r]);          dst = __ldg(&t2[r]);
            }
            __stcs(&out[(size_t)dst * 16u + lane],
                   __ldcs(&mat[(size_t)src * 16u + lane]));
        }
    }
}

extern "C" void kernel_launch(void* const* d_in, const int* in_sizes, int n_in,
                              void* d_out, int out_size)
{
    const float4* m0 = (const float4*)d_in[0];
    const float4* m1 = (const float4*)d_in[1];
    const float4* m2 = (const float4*)d_in[2];
    const int* f0 = (const int*)d_in[3];
    const int* f1 = (const int*)d_in[4];
    const int* f2 = (const int*)d_in[5];
    const int* t0 = (const int*)d_in[6];
    const int* t1 = (const int*)d_in[7];
    const int* t2 = (const int*)d_in[8];

    // Ask for the maximum shared-memory carveout so smem-limited residency
    // reaches the HW cap (attribute set, not an allocation; idempotent).
    static bool attr_done = false;
    if (!attr_done) {
        cudaFuncSetAttribute(multi_index_select_kernel,
                             cudaFuncAttributePreferredSharedMemoryCarveout, 100);
        attr_done = true;
    }

    int L = in_sizes[3];                                 // 400000
    unsigned total = 3u * (unsigned)L * 16u;
    unsigned per_block = THREADS * UNROLL;               // 1280
    unsigned blocks = (total + per_block - 1) / per_block;   // 15000 exact

    multi_index_select_kernel<<<blocks, THREADS>>>(
        m0, m1, m2, f0, f1, f2, t0, t1, t2, (float4*)d_out, L);
}